// round 2
// baseline (speedup 1.0000x reference)
#include <cuda_runtime.h>
#include <math.h>

#define NOBJ 16
#define P    4096
#define EPSF 1e-12f
#define THREADS 128
#define RQ 4                     // queries per thread (registers)
#define QCHUNK (THREADS * RQ)    // 512 queries per CTA
#define NCHUNK (P / QCHUNK)      // 8 chunks per (object, direction)

// Per-object mask (sum(set2) >= 0 ? 1 : 0), written by mask_kernel, read by chamfer_kernel.
__device__ float g_mask[NOBJ];

// ---------------------------------------------------------------------------
// Kernel 1: per-object mask over point_set_2, and zero the output scalar.
// ---------------------------------------------------------------------------
__global__ void mask_kernel(const float* __restrict__ set2, float* __restrict__ out)
{
    const int n = blockIdx.x;
    const float* base = set2 + (size_t)n * P * 2;

    float s = 0.f;
    for (int i = threadIdx.x; i < P * 2; i += blockDim.x) s += base[i];

    // warp reduce
    #pragma unroll
    for (int o = 16; o; o >>= 1) s += __shfl_xor_sync(0xFFFFFFFFu, s, o);

    __shared__ float red[8];
    const int w = threadIdx.x >> 5, l = threadIdx.x & 31;
    if (l == 0) red[w] = s;
    __syncthreads();
    if (w == 0) {
        s = (l < (blockDim.x >> 5)) ? red[l] : 0.f;
        #pragma unroll
        for (int o = 16; o; o >>= 1) s += __shfl_xor_sync(0xFFFFFFFFu, s, o);
        if (l == 0) g_mask[n] = (s >= 0.f) ? 1.f : 0.f;
    }
    if (n == 0 && threadIdx.x == 0) *out = 0.f;   // d_out is poisoned; zero it here
}

// ---------------------------------------------------------------------------
// Kernel 2: chamfer directional min.
// blockIdx = (chunk, object, direction). Targets fully staged in smem with
// precomputed |t|^2. Inner loop per pair: 2 FFMA + 1 FMNMX.
//   d^2(q, t) = s1(q) + [ s2(t) - 2*qx*tx - 2*qy*ty ]   (s1 folded out of the min)
// ---------------------------------------------------------------------------
__global__ void __launch_bounds__(THREADS)
chamfer_kernel(const float* __restrict__ set1, const float* __restrict__ set2,
               float* __restrict__ out)
{
    const int chunk = blockIdx.x;
    const int n     = blockIdx.y;
    const int dir   = blockIdx.z;

    const float* qbase = (dir == 0 ? set1 : set2) + (size_t)n * P * 2;
    const float* tbase = (dir == 0 ? set2 : set1) + (size_t)n * P * 2;

    __shared__ float2 sxy[P];    // 32 KB
    __shared__ float  ss [P];    // 16 KB

    // cooperative stage of the full target set
    const float2* tg = (const float2*)tbase;
    for (int j = threadIdx.x; j < P; j += THREADS) {
        float2 v = tg[j];
        sxy[j] = v;
        ss[j]  = fmaf(v.x, v.x, v.y * v.y);
    }
    __syncthreads();

    // load R queries into registers
    float mx[RQ], my[RQ], s1[RQ], mn[RQ];
    const int q0 = chunk * QCHUNK;
    #pragma unroll
    for (int r = 0; r < RQ; r++) {
        const int q = q0 + r * THREADS + threadIdx.x;
        const float x = qbase[2 * q];
        const float y = qbase[2 * q + 1];
        mx[r] = -2.f * x;
        my[r] = -2.f * y;
        s1[r] = fmaf(x, x, y * y);
        mn[r] = 3.402823e38f;
    }

    // inner loop: 4 targets per iteration, broadcast LDS.128 + LDS.64 pairs
    const float4* xy4 = (const float4*)sxy;   // each float4 = 2 targets' (x,y)
    const float2* sp2 = (const float2*)ss;    // each float2 = 2 targets' s2

    #pragma unroll 2
    for (int j = 0; j < P / 4; j++) {
        const float4 a  = xy4[2 * j];
        const float4 b  = xy4[2 * j + 1];
        const float2 sa = sp2[2 * j];
        const float2 sb = sp2[2 * j + 1];
        #pragma unroll
        for (int r = 0; r < RQ; r++) {
            const float t0 = fmaf(mx[r], a.x, fmaf(my[r], a.y, sa.x));
            const float t1 = fmaf(mx[r], a.z, fmaf(my[r], a.w, sa.y));
            const float t2 = fmaf(mx[r], b.x, fmaf(my[r], b.y, sb.x));
            const float t3 = fmaf(mx[r], b.z, fmaf(my[r], b.w, sb.y));
            mn[r] = fminf(mn[r], fminf(fminf(t0, t1), fminf(t2, t3)));
        }
    }

    // epilogue: sqrt(clip(min d^2, eps)), sum over this thread's queries
    float acc = 0.f;
    #pragma unroll
    for (int r = 0; r < RQ; r++) {
        float d2 = mn[r] + s1[r];
        d2 = fmaxf(d2, EPSF);
        acc += sqrtf(d2);
    }

    // block reduce
    #pragma unroll
    for (int o = 16; o; o >>= 1) acc += __shfl_xor_sync(0xFFFFFFFFu, acc, o);
    __shared__ float red[THREADS / 32];
    if ((threadIdx.x & 31) == 0) red[threadIdx.x >> 5] = acc;
    __syncthreads();
    if (threadIdx.x == 0) {
        float tot = 0.f;
        #pragma unroll
        for (int w = 0; w < THREADS / 32; w++) tot += red[w];
        // weight: mask * 0.5 / (N * P)   (LOSS_WEIGHT = 1)
        atomicAdd(out, tot * g_mask[n] * (0.5f / ((float)NOBJ * (float)P)));
    }
}

// ---------------------------------------------------------------------------
extern "C" void kernel_launch(void* const* d_in, const int* in_sizes, int n_in,
                              void* d_out, int out_size)
{
    const float* set1 = (const float*)d_in[0];
    const float* set2 = (const float*)d_in[1];
    float* out = (float*)d_out;

    mask_kernel<<<NOBJ, 256>>>(set2, out);
    dim3 grid(NCHUNK, NOBJ, 2);
    chamfer_kernel<<<grid, THREADS>>>(set1, set2, out);
}

// round 3
// speedup vs baseline: 1.0732x; 1.0732x over previous
#include <cuda_runtime.h>
#include <math.h>

#define NOBJ 16
#define P    4096
#define EPSF 1e-12f
#define THREADS 128
#define RQ 2                     // queries per thread (registers)
#define QCHUNK (THREADS * RQ)    // 256 queries per CTA
#define NCHUNK (P / QCHUNK)      // 16 chunks per (object, direction) -> grid 512

typedef unsigned long long u64;

__device__ float g_mask[NOBJ];

// ---- packed f32x2 helpers (FFMA2 in SASS; only reachable via PTX) ----------
__device__ __forceinline__ u64 pk2(float lo, float hi) {
    u64 r; asm("mov.b64 %0, {%1, %2};" : "=l"(r) : "f"(lo), "f"(hi)); return r;
}
__device__ __forceinline__ void upk2(u64 v, float& lo, float& hi) {
    asm("mov.b64 {%0, %1}, %2;" : "=f"(lo), "=f"(hi) : "l"(v));
}
__device__ __forceinline__ u64 fma2(u64 a, u64 b, u64 c) {
    u64 d; asm("fma.rn.f32x2 %0, %1, %2, %3;" : "=l"(d) : "l"(a), "l"(b), "l"(c));
    return d;
}

// ---------------------------------------------------------------------------
// Kernel 1: per-object mask over point_set_2, and zero the output scalar.
// ---------------------------------------------------------------------------
__global__ void mask_kernel(const float* __restrict__ set2, float* __restrict__ out)
{
    const int n = blockIdx.x;
    const float* base = set2 + (size_t)n * P * 2;

    float s = 0.f;
    for (int i = threadIdx.x; i < P * 2; i += blockDim.x) s += base[i];

    #pragma unroll
    for (int o = 16; o; o >>= 1) s += __shfl_xor_sync(0xFFFFFFFFu, s, o);

    __shared__ float red[8];
    const int w = threadIdx.x >> 5, l = threadIdx.x & 31;
    if (l == 0) red[w] = s;
    __syncthreads();
    if (w == 0) {
        s = (l < (blockDim.x >> 5)) ? red[l] : 0.f;
        #pragma unroll
        for (int o = 16; o; o >>= 1) s += __shfl_xor_sync(0xFFFFFFFFu, s, o);
        if (l == 0) g_mask[n] = (s >= 0.f) ? 1.f : 0.f;
    }
    if (n == 0 && threadIdx.x == 0) *out = 0.f;   // d_out is poisoned; zero it here
}

// ---------------------------------------------------------------------------
// Kernel 2: chamfer directional min, packed-f32x2 inner loop.
// d^2(q,t) = s1(q) + [ s2(t) - 2qx*tx - 2qy*ty ]  (s1 folded out of the min)
// 4 targets per step as 2 packed lanes: 4x FFMA2 + 4x FMNMX per query.
// ---------------------------------------------------------------------------
__global__ void __launch_bounds__(THREADS)
chamfer_kernel(const float* __restrict__ set1, const float* __restrict__ set2,
               float* __restrict__ out)
{
    const int chunk = blockIdx.x;
    const int n     = blockIdx.y;
    const int dir   = blockIdx.z;

    const float* qbase = (dir == 0 ? set1 : set2) + (size_t)n * P * 2;
    const float* tbase = (dir == 0 ? set2 : set1) + (size_t)n * P * 2;

    __shared__ float sx[P];   // 16 KB  (SoA so packed lanes load contiguously)
    __shared__ float sy[P];   // 16 KB
    __shared__ float ss[P];   // 16 KB

    // cooperative stage of the full target set, SoA + precomputed |t|^2
    const float2* tg = (const float2*)tbase;
    for (int j = threadIdx.x; j < P; j += THREADS) {
        float2 v = tg[j];
        sx[j] = v.x;
        sy[j] = v.y;
        ss[j] = fmaf(v.x, v.x, v.y * v.y);
    }
    __syncthreads();

    // load RQ queries into registers; duplicate -2x / -2y into packed pairs
    u64   mxx[RQ], myy[RQ];
    float s1[RQ], mn[RQ];
    const int q0 = chunk * QCHUNK;
    #pragma unroll
    for (int r = 0; r < RQ; r++) {
        const int q = q0 + r * THREADS + threadIdx.x;
        const float x = qbase[2 * q];
        const float y = qbase[2 * q + 1];
        const float mx = -2.f * x, my = -2.f * y;
        mxx[r] = pk2(mx, mx);
        myy[r] = pk2(my, my);
        s1[r]  = fmaf(x, x, y * y);
        mn[r]  = 3.402823e38f;
    }

    const float4* x4 = (const float4*)sx;   // 4 targets' x per load (broadcast)
    const float4* y4 = (const float4*)sy;
    const float4* s4 = (const float4*)ss;

    #pragma unroll 4
    for (int j = 0; j < P / 4; j++) {
        const float4 xv = x4[j];
        const float4 yv = y4[j];
        const float4 sv = s4[j];
        const u64 xlo = pk2(xv.x, xv.y), xhi = pk2(xv.z, xv.w);
        const u64 ylo = pk2(yv.x, yv.y), yhi = pk2(yv.z, yv.w);
        const u64 slo = pk2(sv.x, sv.y), shi = pk2(sv.z, sv.w);
        #pragma unroll
        for (int r = 0; r < RQ; r++) {
            const u64 d01 = fma2(mxx[r], xlo, fma2(myy[r], ylo, slo));
            const u64 d23 = fma2(mxx[r], xhi, fma2(myy[r], yhi, shi));
            float a, b, c, d;
            upk2(d01, a, b);
            upk2(d23, c, d);
            mn[r] = fminf(mn[r], fminf(fminf(a, b), fminf(c, d)));
        }
    }

    // epilogue: sqrt(clip(min d^2 + s1, eps)), sum this thread's queries
    float acc = 0.f;
    #pragma unroll
    for (int r = 0; r < RQ; r++) {
        float d2 = mn[r] + s1[r];
        d2 = fmaxf(d2, EPSF);
        acc += sqrtf(d2);
    }

    // block reduce
    #pragma unroll
    for (int o = 16; o; o >>= 1) acc += __shfl_xor_sync(0xFFFFFFFFu, acc, o);
    __shared__ float red[THREADS / 32];
    if ((threadIdx.x & 31) == 0) red[threadIdx.x >> 5] = acc;
    __syncthreads();
    if (threadIdx.x == 0) {
        float tot = 0.f;
        #pragma unroll
        for (int w = 0; w < THREADS / 32; w++) tot += red[w];
        atomicAdd(out, tot * g_mask[n] * (0.5f / ((float)NOBJ * (float)P)));
    }
}

// ---------------------------------------------------------------------------
extern "C" void kernel_launch(void* const* d_in, const int* in_sizes, int n_in,
                              void* d_out, int out_size)
{
    const float* set1 = (const float*)d_in[0];
    const float* set2 = (const float*)d_in[1];
    float* out = (float*)d_out;

    mask_kernel<<<NOBJ, 256>>>(set2, out);
    dim3 grid(NCHUNK, NOBJ, 2);
    chamfer_kernel<<<grid, THREADS>>>(set1, set2, out);
}

// round 4
// speedup vs baseline: 1.1675x; 1.0878x over previous
#include <cuda_runtime.h>
#include <math.h>

#define NOBJ 16
#define P    4096
#define EPSF 1e-12f
#define THREADS 64
#define RQ 4                     // queries per thread (registers)
#define QCHUNK (THREADS * RQ)    // 256 queries per CTA
#define NCHUNK (P / QCHUNK)      // 16 chunks -> grid 16*16*2 = 512 CTAs

typedef unsigned long long u64;

__device__ float g_mask[NOBJ];

// ---- packed f32x2 helpers ---------------------------------------------------
__device__ __forceinline__ u64 pk2(float lo, float hi) {
    u64 r; asm("mov.b64 %0, {%1, %2};" : "=l"(r) : "f"(lo), "f"(hi)); return r;
}
__device__ __forceinline__ void upk2(u64 v, float& lo, float& hi) {
    asm("mov.b64 {%0, %1}, %2;" : "=f"(lo), "=f"(hi) : "l"(v));
}
__device__ __forceinline__ u64 fma2(u64 a, u64 b, u64 c) {
    u64 d; asm("fma.rn.f32x2 %0, %1, %2, %3;" : "=l"(d) : "l"(a), "l"(b), "l"(c));
    return d;
}

// ---------------------------------------------------------------------------
// Kernel 1: per-object mask over point_set_2, and zero the output scalar.
// ---------------------------------------------------------------------------
__global__ void mask_kernel(const float* __restrict__ set2, float* __restrict__ out)
{
    const int n = blockIdx.x;
    const float* base = set2 + (size_t)n * P * 2;

    float s = 0.f;
    for (int i = threadIdx.x; i < P * 2; i += blockDim.x) s += base[i];

    #pragma unroll
    for (int o = 16; o; o >>= 1) s += __shfl_xor_sync(0xFFFFFFFFu, s, o);

    __shared__ float red[8];
    const int w = threadIdx.x >> 5, l = threadIdx.x & 31;
    if (l == 0) red[w] = s;
    __syncthreads();
    if (w == 0) {
        s = (l < (blockDim.x >> 5)) ? red[l] : 0.f;
        #pragma unroll
        for (int o = 16; o; o >>= 1) s += __shfl_xor_sync(0xFFFFFFFFu, s, o);
        if (l == 0) g_mask[n] = (s >= 0.f) ? 1.f : 0.f;
    }
    if (n == 0 && threadIdx.x == 0) *out = 0.f;   // d_out is poisoned; zero it here
}

// ---------------------------------------------------------------------------
// Kernel 2: chamfer directional min.
// SoA shared staging; inner loop loads ulonglong2 (4 targets) per array —
// the two u64 halves feed fma.rn.f32x2 DIRECTLY (no repacking MOVs).
// d^2(q,t) = s1(q) + [ s2(t) - 2qx*tx - 2qy*ty ]   (s1 folded out of the min)
// Per 4 targets per query: 4 FFMA2 (fma pipe) + 4 FMNMX (alu pipe).
// ---------------------------------------------------------------------------
__global__ void __launch_bounds__(THREADS)
chamfer_kernel(const float* __restrict__ set1, const float* __restrict__ set2,
               float* __restrict__ out)
{
    const int chunk = blockIdx.x;
    const int n     = blockIdx.y;
    const int dir   = blockIdx.z;

    const float* qbase = (dir == 0 ? set1 : set2) + (size_t)n * P * 2;
    const float* tbase = (dir == 0 ? set2 : set1) + (size_t)n * P * 2;

    __shared__ __align__(16) float sx[P];   // 16 KB
    __shared__ __align__(16) float sy[P];   // 16 KB
    __shared__ __align__(16) float ss[P];   // 16 KB

    // cooperative stage: 2 points per thread-iter via float4 load
    const float4* tg4 = (const float4*)tbase;    // (x0,y0,x1,y1)
    for (int j = threadIdx.x; j < P / 2; j += THREADS) {
        float4 v = tg4[j];
        *(float2*)&sx[2 * j] = make_float2(v.x, v.z);
        *(float2*)&sy[2 * j] = make_float2(v.y, v.w);
        *(float2*)&ss[2 * j] = make_float2(fmaf(v.x, v.x, v.y * v.y),
                                           fmaf(v.z, v.z, v.w * v.w));
    }
    __syncthreads();

    // load RQ queries; duplicate -2x / -2y into packed operands
    u64   mxx[RQ], myy[RQ];
    float s1[RQ], mn[RQ];
    const int q0 = chunk * QCHUNK;
    #pragma unroll
    for (int r = 0; r < RQ; r++) {
        const int q = q0 + r * THREADS + threadIdx.x;
        const float x = qbase[2 * q];
        const float y = qbase[2 * q + 1];
        const float mx = -2.f * x, my = -2.f * y;
        mxx[r] = pk2(mx, mx);
        myy[r] = pk2(my, my);
        s1[r]  = fmaf(x, x, y * y);
        mn[r]  = 3.402823e38f;
    }

    const ulonglong2* xp = (const ulonglong2*)sx;   // element j = targets 4j..4j+3
    const ulonglong2* yp = (const ulonglong2*)sy;
    const ulonglong2* sp = (const ulonglong2*)ss;

    #pragma unroll 8
    for (int j = 0; j < P / 4; j++) {
        const ulonglong2 X = xp[j];
        const ulonglong2 Y = yp[j];
        const ulonglong2 S = sp[j];
        #pragma unroll
        for (int r = 0; r < RQ; r++) {
            const u64 d01 = fma2(mxx[r], X.x, fma2(myy[r], Y.x, S.x));
            const u64 d23 = fma2(mxx[r], X.y, fma2(myy[r], Y.y, S.y));
            float a, b, c, d;
            upk2(d01, a, b);
            upk2(d23, c, d);
            mn[r] = fminf(mn[r], fminf(fminf(a, b), fminf(c, d)));
        }
    }

    // epilogue: sqrt(clip(min d^2 + s1, eps)), sum this thread's queries
    float acc = 0.f;
    #pragma unroll
    for (int r = 0; r < RQ; r++) {
        float d2 = mn[r] + s1[r];
        d2 = fmaxf(d2, EPSF);
        acc += sqrtf(d2);
    }

    // block reduce (2 warps)
    #pragma unroll
    for (int o = 16; o; o >>= 1) acc += __shfl_xor_sync(0xFFFFFFFFu, acc, o);
    __shared__ float red[THREADS / 32];
    if ((threadIdx.x & 31) == 0) red[threadIdx.x >> 5] = acc;
    __syncthreads();
    if (threadIdx.x == 0) {
        float tot = 0.f;
        #pragma unroll
        for (int w = 0; w < THREADS / 32; w++) tot += red[w];
        atomicAdd(out, tot * g_mask[n] * (0.5f / ((float)NOBJ * (float)P)));
    }
}

// ---------------------------------------------------------------------------
extern "C" void kernel_launch(void* const* d_in, const int* in_sizes, int n_in,
                              void* d_out, int out_size)
{
    const float* set1 = (const float*)d_in[0];
    const float* set2 = (const float*)d_in[1];
    float* out = (float*)d_out;

    mask_kernel<<<NOBJ, 256>>>(set2, out);
    dim3 grid(NCHUNK, NOBJ, 2);
    chamfer_kernel<<<grid, THREADS>>>(set1, set2, out);
}